// round 13
// baseline (speedup 1.0000x reference)
#include <cuda_runtime.h>
#include <cstdint>
#include <cstddef>

#define B_ 512
#define K_ 128
#define D_ 512

// Scratch (static device globals — no allocation anywhere).
__device__ float    g_cost[(size_t)B_ * K_ * K_]; // 32 MB
__device__ int      g_perm[B_ * K_];              // row -> matched column
__device__ double   g_part[B_];                   // per-batch loss partial
__device__ unsigned g_ticket;                     // 0-init; self-resetting
__device__ unsigned g_done;                       // 0-init; self-resetting

// ---------------------------------------------------------------------------
// tf32 mma.sync.m16n8k8 (raw fp32 bits as tf32, RZ truncation).
// ---------------------------------------------------------------------------
__device__ __forceinline__ void mma_tf32(float* c, unsigned a0, unsigned a1,
                                         unsigned a2, unsigned a3,
                                         unsigned b0, unsigned b1)
{
    asm volatile(
        "mma.sync.aligned.m16n8k8.row.col.f32.tf32.tf32.f32 "
        "{%0,%1,%2,%3}, {%4,%5,%6,%7}, {%8,%9}, {%0,%1,%2,%3};"
        : "+f"(c[0]), "+f"(c[1]), "+f"(c[2]), "+f"(c[3])
        : "r"(a0), "r"(a1), "r"(a2), "r"(a3), "r"(b0), "r"(b1));
}

__device__ __forceinline__ void cp16(unsigned dst, const void* src)
{
    asm volatile("cp.async.cg.shared.global [%0], [%1], 16;"
                 :: "r"(dst), "l"(src));
}

#define KT 16                       // cost k-tile
#define PSTR 20                     // padded stride (floats); 80B rows, 16B aligned
#define BUF_FLOATS (K_ * PSTR)      // 2560 floats per matrix per buffer
#define COST_SMEM (4 * BUF_FLOATS * 4)   // 40 KB: 2 buffers x {x,y}

// ---------------------------------------------------------------------------
// Kernel 1: cost matrix, one CTA (4 warps) per batch, cp.async double-buffered
// tf32 MMA. Validated (R10-R12, ~152us).
// ---------------------------------------------------------------------------
__global__ void __launch_bounds__(128, 3) cost_kernel(const float* __restrict__ X,
                                                      const float* __restrict__ Y)
{
    extern __shared__ char smem_raw[];
    __shared__ float sn[2][K_];

    int b = blockIdx.x;
    int tid = threadIdx.x;
    int w = tid >> 5, lane = tid & 31;
    const float* x = X + (size_t)b * K_ * D_;
    const float* y = Y + (size_t)b * K_ * D_;

    float* stage = reinterpret_cast<float*>(smem_raw);
    unsigned stage_s = (unsigned)__cvta_generic_to_shared(stage);
    float* cb = g_cost + (size_t)b * K_ * K_;

    // Issue tile 0 loads immediately.
    {
        unsigned xb = stage_s;
        unsigned yb = xb + BUF_FLOATS * 4;
        #pragma unroll
        for (int l = 0; l < 4; ++l) {
            int cid = tid + l * 128;
            int row = cid >> 2, c4 = cid & 3;
            cp16(xb + (unsigned)(row * PSTR + c4 * 4) * 4,
                 x + (size_t)row * D_ + c4 * 4);
            cp16(yb + (unsigned)(row * PSTR + c4 * 4) * 4,
                 y + (size_t)row * D_ + c4 * 4);
        }
        asm volatile("cp.async.commit_group;");
    }

    // Row squared norms (exact fp32), overlapped with tile-0 flight.
    {
        const float4* px = reinterpret_cast<const float4*>(x + (size_t)tid * D_);
        const float4* py = reinterpret_cast<const float4*>(y + (size_t)tid * D_);
        float s0 = 0.f, s1 = 0.f;
        #pragma unroll 8
        for (int k = 0; k < D_ / 4; ++k) {
            float4 a = px[k];
            s0 += a.x * a.x + a.y * a.y + a.z * a.z + a.w * a.w;
            float4 c = py[k];
            s1 += c.x * c.x + c.y * c.y + c.z * c.z + c.w * c.w;
        }
        sn[0][tid] = s0;
        sn[1][tid] = s1;
    }

    int g = lane >> 2, tig = lane & 3;
    int m0 = w * 32;

    float acc[2][16][4];
    #pragma unroll
    for (int mt = 0; mt < 2; ++mt)
        #pragma unroll
        for (int nt = 0; nt < 16; ++nt)
            #pragma unroll
            for (int q = 0; q < 4; ++q) acc[mt][nt][q] = 0.f;

    const int NT_TILES = D_ / KT;    // 32
    for (int t = 0; t < NT_TILES; ++t) {
        if (t + 1 < NT_TILES) {
            int k0 = (t + 1) * KT;
            unsigned xb = stage_s + (unsigned)(((t + 1) & 1) * 2 * BUF_FLOATS) * 4;
            unsigned yb = xb + BUF_FLOATS * 4;
            #pragma unroll
            for (int l = 0; l < 4; ++l) {
                int cid = tid + l * 128;
                int row = cid >> 2, c4 = cid & 3;
                cp16(xb + (unsigned)(row * PSTR + c4 * 4) * 4,
                     x + (size_t)row * D_ + k0 + c4 * 4);
                cp16(yb + (unsigned)(row * PSTR + c4 * 4) * 4,
                     y + (size_t)row * D_ + k0 + c4 * 4);
            }
        }
        asm volatile("cp.async.commit_group;");   // uniform group count
        asm volatile("cp.async.wait_group 1;");   // tile t resident
        __syncthreads();

        const float* xs = stage + (t & 1) * 2 * BUF_FLOATS;
        const float* ys = xs + BUF_FLOATS;

        #pragma unroll
        for (int ks = 0; ks < KT; ks += 8) {
            unsigned a[2][4];
            #pragma unroll
            for (int mt = 0; mt < 2; ++mt) {
                int r = m0 + mt * 16 + g;
                a[mt][0] = __float_as_uint(xs[r * PSTR + ks + tig]);
                a[mt][1] = __float_as_uint(xs[(r + 8) * PSTR + ks + tig]);
                a[mt][2] = __float_as_uint(xs[r * PSTR + ks + tig + 4]);
                a[mt][3] = __float_as_uint(xs[(r + 8) * PSTR + ks + tig + 4]);
            }
            #pragma unroll
            for (int nt = 0; nt < 16; ++nt) {
                int cn = nt * 8 + g;
                unsigned b0 = __float_as_uint(ys[cn * PSTR + ks + tig]);
                unsigned b1 = __float_as_uint(ys[cn * PSTR + ks + tig + 4]);
                mma_tf32(acc[0][nt], a[0][0], a[0][1], a[0][2], a[0][3], b0, b1);
                mma_tf32(acc[1][nt], a[1][0], a[1][1], a[1][2], a[1][3], b0, b1);
            }
        }
        __syncthreads();   // compute done before buffer reuse next iter
    }

    // Epilogue -> g_cost
    #pragma unroll
    for (int mt = 0; mt < 2; ++mt) {
        int i0r = m0 + mt * 16 + g;
        float sx0 = sn[0][i0r];
        float sx1 = sn[0][i0r + 8];
        #pragma unroll
        for (int nt = 0; nt < 16; ++nt) {
            int j = nt * 8 + 2 * tig;
            float sy0 = sn[1][j], sy1 = sn[1][j + 1];
            float2 o0, o1;
            o0.x = sx0 + sy0 - 2.f * acc[mt][nt][0];
            o0.y = sx0 + sy1 - 2.f * acc[mt][nt][1];
            o1.x = sx1 + sy0 - 2.f * acc[mt][nt][2];
            o1.y = sx1 + sy1 - 2.f * acc[mt][nt][3];
            *reinterpret_cast<float2*>(&cb[(size_t)i0r * K_ + j])       = o0;
            *reinterpret_cast<float2*>(&cb[(size_t)(i0r + 8) * K_ + j]) = o1;
        }
    }
}

// ---------------------------------------------------------------------------
// Kernel 2: JV solver — 3 INDEPENDENT solver warps per CTA (96 threads) so
// they land on SMSPs 0/1/2 instead of all piling onto SMSP 0 (wid % 4 rule;
// 32-thread CTAs put every solver warp on scheduler 0 and leave 3 idle).
// 192KB dynamic smem = 3 cost matrices; per-warp u/rowclaim/q instances.
// Per-warp ticket work stealing; replay-safe counter reset.
// ---------------------------------------------------------------------------
#define HGRID 148
#define NWARP 3
#define SOLVER_SMEM (NWARP * K_ * K_ * 4)   // 192 KB

__global__ void __launch_bounds__(32 * NWARP, 1)
hungarian_kernel()
{
    extern __shared__ float cost_all[];     // NWARP * K_*K_ floats
    __shared__ float u_sh[NWARP][K_ + 4];
    __shared__ int   rc_sh[NWARP][K_];
    __shared__ int   q_sh[NWARP][4 * K_ + 8];

    const unsigned FULL = 0xFFFFFFFFu;
    int wid = threadIdx.x >> 5;             // 0..2 -> SMSP 0..2
    int L = threadIdx.x & 31;

    float* cost_s  = cost_all + (size_t)wid * K_ * K_;
    float* u_s     = u_sh[wid];
    int*   rowclaim = rc_sh[wid];
    int*   q_s     = q_sh[wid];

    while (true) {
        unsigned tkt;
        if (L == 0) tkt = atomicAdd(&g_ticket, 1);
        tkt = __shfl_sync(FULL, tkt, 0);
        if (tkt >= B_) break;
        int b = (int)tkt;

        // ---- Stage cost matrix; fold column-reduction into the copy. ----
        float cm0 = 3.0e38f, cm1 = 3.0e38f, cm2 = 3.0e38f, cm3 = 3.0e38f;
        int   am0 = 0, am1 = 0, am2 = 0, am3 = 0;
        {
            const float4* src = reinterpret_cast<const float4*>(g_cost + (size_t)b * K_ * K_);
            float4* dst = reinterpret_cast<float4*>(cost_s);
            #pragma unroll 8
            for (int q = 0; q < K_; ++q) {
                float4 vv = src[L + 32 * q];
                dst[L + 32 * q] = vv;
                if (vv.x < cm0) { cm0 = vv.x; am0 = q; }
                if (vv.y < cm1) { cm1 = vv.y; am1 = q; }
                if (vv.z < cm2) { cm2 = vv.z; am2 = q; }
                if (vv.w < cm3) { cm3 = vv.w; am3 = q; }
            }
        }
        #pragma unroll
        for (int c = 0; c < 4; ++c) {
            u_s[1 + L + 32 * c] = 0.f;
            rowclaim[L + 32 * c] = -1;
        }
        if (L == 0) u_s[0] = 0.f;
        __syncwarp();

        // ---- Greedy claim. ----
        float v[4] = {cm0, cm1, cm2, cm3};
        int am[4] = {am0, am1, am2, am3};
        unsigned pcol_pack = 0;          // 4x8-bit: p[4L+c] (row id 1..128, 0=free)
        #pragma unroll
        for (int c = 0; c < 4; ++c) {
            if (atomicCAS(&rowclaim[am[c]], -1, 4 * L + c) == -1)
                pcol_pack |= (unsigned)(am[c] + 1) << (8 * c);
        }
        __syncwarp();

        // ---- Augmenting row reduction (lapjv ARR). ----
        {
            if (L == 0) {
                int n = 0;
                for (int r = 0; r < K_; ++r)
                    if (rowclaim[r] < 0) q_s[n++] = r + 1;
                q_s[4 * K_ + 4] = n;
            }
            __syncwarp();
            int qlen = q_s[4 * K_ + 4];
            int k = 0;
            int iters = 0;
            const int cap = 3 * K_;
            while (k < qlen && iters < cap) {
                ++iters;
                int i = q_s[k]; ++k;
                const float* crow = cost_s + (size_t)(i - 1) * K_;
                float4 c4 = *reinterpret_cast<const float4*>(crow + 4 * L);
                float r0 = fmaxf(c4.x - v[0], 0.f), r1 = fmaxf(c4.y - v[1], 0.f);
                float r2 = fmaxf(c4.z - v[2], 0.f), r3 = fmaxf(c4.w - v[3], 0.f);
                float lm1 = r0, lm2 = 3.0e38f; int lc = 0, lc2 = 1;
                if (r1 < lm1) { lm2 = lm1; lc2 = lc; lm1 = r1; lc = 1; }
                else          { lm2 = r1; lc2 = 1; }
                if (r2 < lm1) { lm2 = lm1; lc2 = lc; lm1 = r2; lc = 2; }
                else if (r2 < lm2) { lm2 = r2; lc2 = 2; }
                if (r3 < lm1) { lm2 = lm1; lc2 = lc; lm1 = r3; lc = 3; }
                else if (r3 < lm2) { lm2 = r3; lc2 = 3; }

                unsigned k1 = (__float_as_uint(lm1) & 0xFFFFFF00u) | (unsigned)(4 * L + lc);
                unsigned m1 = __reduce_min_sync(FULL, k1);
                int j1_0 = m1 & 0xFF;
                int wl1 = j1_0 >> 2;
                unsigned k2 = (L == wl1)
                    ? ((__float_as_uint(lm2) & 0xFFFFFF00u) | (unsigned)(4 * L + lc2))
                    : k1;
                unsigned m2 = __reduce_min_sync(FULL, k2);
                int j2_0 = m2 & 0xFF;
                float u1 = __uint_as_float(m1 & 0xFFFFFF00u);
                float u2 = __uint_as_float(m2 & 0xFFFFFF00u);
                bool strict = (m1 >> 8) < (m2 >> 8);

                unsigned pp1 = __shfl_sync(FULL, pcol_pack, wl1);
                int i0 = (pp1 >> (8 * (j1_0 & 3))) & 0xFF;
                int jt_0;
                if (strict) {
                    #pragma unroll
                    for (int c = 0; c < 4; ++c)
                        if (L == wl1 && c == (j1_0 & 3)) v[c] -= (u2 - u1);
                    jt_0 = j1_0;
                } else if (i0 != 0) {
                    jt_0 = j2_0;
                } else {
                    jt_0 = j1_0;
                }
                int ownt = jt_0 >> 2, slt = jt_0 & 3;
                unsigned ppt = __shfl_sync(FULL, pcol_pack, ownt);
                int idisp = (ppt >> (8 * slt)) & 0xFF;
                if (L == ownt)
                    pcol_pack = (pcol_pack & ~(0xFFu << (8 * slt)))
                              | ((unsigned)i << (8 * slt));
                if (L == 0) {
                    u_s[i] = u2;
                    rowclaim[i - 1] = jt_0;
                }
                if (idisp != 0) {
                    if (L == 0) rowclaim[idisp - 1] = -1;
                    if (strict) { --k; if (L == 0) q_s[k] = idisp; }
                    else        { if (L == 0) q_s[qlen] = idisp; ++qlen; }
                }
                __syncwarp();
            }
        }

        // ---- Dijkstra phases for remaining free rows. ----
        for (int i = 1; i <= K_; ++i) {
            if (rowclaim[i - 1] >= 0) continue;

            float minv[4] = {3.0e38f, 3.0e38f, 3.0e38f, 3.0e38f};
            unsigned way_pack = 0;
            unsigned used = 0;
            float urow[4];
            #pragma unroll
            for (int c = 0; c < 4; ++c)
                urow[c] = u_s[(pcol_pack >> (8 * c)) & 0xFFu];
            float ui_new = u_s[i];

            int j0 = 0, i0 = i;
            float ui0 = ui_new;
            int jfin;
            while (true) {
                float4 cr4 = *reinterpret_cast<const float4*>(
                    cost_s + (size_t)(i0 - 1) * K_ + 4 * L);
                float cr[4] = {cr4.x, cr4.y, cr4.z, cr4.w};

                unsigned key = 0xFFFFFFFFu;
                float bu = 0.f;
                #pragma unroll
                for (int c = 0; c < 4; ++c) {
                    bool fr = !((used >> c) & 1u);
                    float cur = fmaxf(cr[c] - ui0 - v[c], 0.f);
                    if (fr) {
                        if (cur < minv[c]) {
                            minv[c] = cur;
                            way_pack = (way_pack & ~(0xFFu << (8 * c)))
                                     | ((unsigned)j0 << (8 * c));
                        }
                        unsigned kc = (__float_as_uint(minv[c]) & 0xFFFFFF00u)
                                    | (unsigned)(4 * L + c);
                        if (kc < key) { key = kc; bu = urow[c]; }
                    }
                }
                unsigned m = __reduce_min_sync(FULL, key);
                int j1_0 = m & 0xFF;
                int wl = j1_0 >> 2, slot = j1_0 & 3;
                float ui1   = __shfl_sync(FULL, bu, wl);
                unsigned pp = __shfl_sync(FULL, pcol_pack, wl);
                int pj1 = (pp >> (8 * slot)) & 0xFF;
                float delta = __uint_as_float(m & 0xFFFFFF00u);
                #pragma unroll
                for (int c = 0; c < 4; ++c) {
                    if ((used >> c) & 1u) { urow[c] += delta; v[c] -= delta; }
                    else                  { minv[c] -= delta; }
                }
                ui_new += delta;
                if (L == wl) used |= 1u << slot;
                if (pj1 == 0) { jfin = j1_0 + 1; break; }
                j0 = j1_0 + 1; i0 = pj1; ui0 = ui1;
            }

            #pragma unroll
            for (int c = 0; c < 4; ++c)
                if ((used >> c) & 1u)
                    u_s[(pcol_pack >> (8 * c)) & 0xFFu] = urow[c];
            if (L == 0) u_s[i] = ui_new;

            int jj = jfin;
            while (jj) {
                int idx = jj - 1;
                unsigned wp = __shfl_sync(FULL, way_pack, idx >> 2);
                int jprev = (wp >> (8 * (idx & 3))) & 0xFFu;
                int pv;
                if (jprev == 0) pv = i;
                else {
                    int idx2 = jprev - 1;
                    unsigned pp2 = __shfl_sync(FULL, pcol_pack, idx2 >> 2);
                    pv = (pp2 >> (8 * (idx2 & 3))) & 0xFFu;
                }
                if ((idx >> 2) == L) {
                    int sl = idx & 3;
                    pcol_pack = (pcol_pack & ~(0xFFu << (8 * sl)))
                              | ((unsigned)pv << (8 * sl));
                }
                jj = jprev;
            }
            if (L == 0) rowclaim[i - 1] = 0;
            __syncwarp();
        }

        // ---- g_perm[p[j]-1] = j (0-based). ----
        #pragma unroll
        for (int c = 0; c < 4; ++c) {
            int pr = (pcol_pack >> (8 * c)) & 0xFFu;    // row id 1..128
            g_perm[b * K_ + (pr - 1)] = 4 * L + c;
        }
        __syncwarp();
    }

    // Replay-safe counter reset: every solver WARP bumps g_done once on exit;
    // the last of gridDim.x * NWARP resets both counters.
    if (L == 0) {
        __threadfence();
        unsigned d = atomicAdd(&g_done, 1) + 1;
        if (d == gridDim.x * NWARP) {
            atomicExch(&g_ticket, 0u);
            atomicExch(&g_done, 0u);
        }
    }
}

// ---------------------------------------------------------------------------
// Kernel 3: exact MSE partials per batch (fp32 diffs like reference).
// ---------------------------------------------------------------------------
__global__ void __launch_bounds__(256) loss_kernel(const float* __restrict__ X,
                                                   const float* __restrict__ Y)
{
    int b = blockIdx.x;
    int tid = threadIdx.x, lane = tid & 31, w = tid >> 5;
    const float* x = X + (size_t)b * K_ * D_;
    const float* y = Y + (size_t)b * K_ * D_;

    float s = 0.f;
    for (int i = w; i < K_; i += 8) {
        int c = g_perm[b * K_ + i];
        const float4* xp = reinterpret_cast<const float4*>(x + (size_t)i * D_);
        const float4* yp = reinterpret_cast<const float4*>(y + (size_t)c * D_);
        #pragma unroll
        for (int q = 0; q < 4; ++q) {
            float4 a  = xp[lane + q * 32];
            float4 bb = yp[lane + q * 32];
            float dx = a.x - bb.x, dy = a.y - bb.y;
            float dz = a.z - bb.z, dw = a.w - bb.w;
            s += dx * dx + dy * dy + dz * dz + dw * dw;
        }
    }
    double ds = (double)s;
    #pragma unroll
    for (int off = 16; off; off >>= 1)
        ds += __shfl_down_sync(0xFFFFFFFFu, ds, off);
    __shared__ double wsum[8];
    if (lane == 0) wsum[w] = ds;
    __syncthreads();
    if (tid == 0) {
        double tot = 0.0;
        #pragma unroll
        for (int q = 0; q < 8; ++q) tot += wsum[q];
        g_part[b] = tot;
    }
}

__global__ void __launch_bounds__(512) final_kernel(float* __restrict__ out)
{
    __shared__ double s[512];
    int t = threadIdx.x;
    s[t] = g_part[t];
    __syncthreads();
    for (int stride = 256; stride; stride >>= 1) {
        if (t < stride) s[t] += s[t + stride];
        __syncthreads();
    }
    if (t == 0) out[0] = (float)(s[0] / ((double)B_ * K_ * D_));
}

// ---------------------------------------------------------------------------
extern "C" void kernel_launch(void* const* d_in, const int* in_sizes, int n_in,
                              void* d_out, int out_size)
{
    (void)in_sizes; (void)n_in; (void)out_size;
    const float* X = (const float*)d_in[0];
    const float* Y = (const float*)d_in[1];
    float* out = (float*)d_out;

    cudaFuncSetAttribute(hungarian_kernel,
                         cudaFuncAttributeMaxDynamicSharedMemorySize,
                         SOLVER_SMEM);

    cost_kernel<<<B_, 128, COST_SMEM>>>(X, Y);
    hungarian_kernel<<<HGRID, 32 * NWARP, SOLVER_SMEM>>>();
    loss_kernel<<<B_, 256>>>(X, Y);
    final_kernel<<<1, 512>>>(out);
}

// round 14
// speedup vs baseline: 1.7261x; 1.7261x over previous
#include <cuda_runtime.h>
#include <cstdint>
#include <cstddef>

#define B_ 512
#define K_ 128
#define D_ 512

// Scratch (static device globals — no allocation anywhere).
__device__ float  g_cost[(size_t)B_ * K_ * K_];   // 32 MB
__device__ double g_part[B_];                     // per-batch assignment cost

// ---------------------------------------------------------------------------
// tf32 mma.sync.m16n8k8 (raw fp32 bits as tf32, RZ truncation).
// ---------------------------------------------------------------------------
__device__ __forceinline__ void mma_tf32(float* c, unsigned a0, unsigned a1,
                                         unsigned a2, unsigned a3,
                                         unsigned b0, unsigned b1)
{
    asm volatile(
        "mma.sync.aligned.m16n8k8.row.col.f32.tf32.tf32.f32 "
        "{%0,%1,%2,%3}, {%4,%5,%6,%7}, {%8,%9}, {%0,%1,%2,%3};"
        : "+f"(c[0]), "+f"(c[1]), "+f"(c[2]), "+f"(c[3])
        : "r"(a0), "r"(a1), "r"(a2), "r"(a3), "r"(b0), "r"(b1));
}

__device__ __forceinline__ void cp16(unsigned dst, const void* src)
{
    asm volatile("cp.async.cg.shared.global [%0], [%1], 16;"
                 :: "r"(dst), "l"(src));
}

#define KT 16                       // cost k-tile
#define PSTR 20                     // padded stride (floats); 80B rows, 16B aligned
#define BUF_FLOATS (K_ * PSTR)      // 2560 floats per matrix per buffer
#define COST_SMEM (4 * BUF_FLOATS * 4)   // 40 KB: 2 buffers x {x,y}

// ---------------------------------------------------------------------------
// Kernel 1: cost matrix, one CTA (4 warps) per batch, cp.async double-buffered
// tf32 MMA. Validated (R10-R13, ~152us).
// ---------------------------------------------------------------------------
__global__ void __launch_bounds__(128, 3) cost_kernel(const float* __restrict__ X,
                                                      const float* __restrict__ Y)
{
    extern __shared__ char smem_raw[];
    __shared__ float sn[2][K_];

    int b = blockIdx.x;
    int tid = threadIdx.x;
    int w = tid >> 5, lane = tid & 31;
    const float* x = X + (size_t)b * K_ * D_;
    const float* y = Y + (size_t)b * K_ * D_;

    float* stage = reinterpret_cast<float*>(smem_raw);
    unsigned stage_s = (unsigned)__cvta_generic_to_shared(stage);
    float* cb = g_cost + (size_t)b * K_ * K_;

    // Issue tile 0 loads immediately.
    {
        unsigned xb = stage_s;
        unsigned yb = xb + BUF_FLOATS * 4;
        #pragma unroll
        for (int l = 0; l < 4; ++l) {
            int cid = tid + l * 128;
            int row = cid >> 2, c4 = cid & 3;
            cp16(xb + (unsigned)(row * PSTR + c4 * 4) * 4,
                 x + (size_t)row * D_ + c4 * 4);
            cp16(yb + (unsigned)(row * PSTR + c4 * 4) * 4,
                 y + (size_t)row * D_ + c4 * 4);
        }
        asm volatile("cp.async.commit_group;");
    }

    // Row squared norms (exact fp32), overlapped with tile-0 flight.
    {
        const float4* px = reinterpret_cast<const float4*>(x + (size_t)tid * D_);
        const float4* py = reinterpret_cast<const float4*>(y + (size_t)tid * D_);
        float s0 = 0.f, s1 = 0.f;
        #pragma unroll 8
        for (int k = 0; k < D_ / 4; ++k) {
            float4 a = px[k];
            s0 += a.x * a.x + a.y * a.y + a.z * a.z + a.w * a.w;
            float4 c = py[k];
            s1 += c.x * c.x + c.y * c.y + c.z * c.z + c.w * c.w;
        }
        sn[0][tid] = s0;
        sn[1][tid] = s1;
    }

    int g = lane >> 2, tig = lane & 3;
    int m0 = w * 32;

    float acc[2][16][4];
    #pragma unroll
    for (int mt = 0; mt < 2; ++mt)
        #pragma unroll
        for (int nt = 0; nt < 16; ++nt)
            #pragma unroll
            for (int q = 0; q < 4; ++q) acc[mt][nt][q] = 0.f;

    const int NT_TILES = D_ / KT;    // 32
    for (int t = 0; t < NT_TILES; ++t) {
        if (t + 1 < NT_TILES) {
            int k0 = (t + 1) * KT;
            unsigned xb = stage_s + (unsigned)(((t + 1) & 1) * 2 * BUF_FLOATS) * 4;
            unsigned yb = xb + BUF_FLOATS * 4;
            #pragma unroll
            for (int l = 0; l < 4; ++l) {
                int cid = tid + l * 128;
                int row = cid >> 2, c4 = cid & 3;
                cp16(xb + (unsigned)(row * PSTR + c4 * 4) * 4,
                     x + (size_t)row * D_ + k0 + c4 * 4);
                cp16(yb + (unsigned)(row * PSTR + c4 * 4) * 4,
                     y + (size_t)row * D_ + k0 + c4 * 4);
            }
        }
        asm volatile("cp.async.commit_group;");   // uniform group count
        asm volatile("cp.async.wait_group 1;");   // tile t resident
        __syncthreads();

        const float* xs = stage + (t & 1) * 2 * BUF_FLOATS;
        const float* ys = xs + BUF_FLOATS;

        #pragma unroll
        for (int ks = 0; ks < KT; ks += 8) {
            unsigned a[2][4];
            #pragma unroll
            for (int mt = 0; mt < 2; ++mt) {
                int r = m0 + mt * 16 + g;
                a[mt][0] = __float_as_uint(xs[r * PSTR + ks + tig]);
                a[mt][1] = __float_as_uint(xs[(r + 8) * PSTR + ks + tig]);
                a[mt][2] = __float_as_uint(xs[r * PSTR + ks + tig + 4]);
                a[mt][3] = __float_as_uint(xs[(r + 8) * PSTR + ks + tig + 4]);
            }
            #pragma unroll
            for (int nt = 0; nt < 16; ++nt) {
                int cn = nt * 8 + g;
                unsigned b0 = __float_as_uint(ys[cn * PSTR + ks + tig]);
                unsigned b1 = __float_as_uint(ys[cn * PSTR + ks + tig + 4]);
                mma_tf32(acc[0][nt], a[0][0], a[0][1], a[0][2], a[0][3], b0, b1);
                mma_tf32(acc[1][nt], a[1][0], a[1][1], a[1][2], a[1][3], b0, b1);
            }
        }
        __syncthreads();   // compute done before buffer reuse next iter
    }

    // Epilogue -> g_cost
    #pragma unroll
    for (int mt = 0; mt < 2; ++mt) {
        int i0r = m0 + mt * 16 + g;
        float sx0 = sn[0][i0r];
        float sx1 = sn[0][i0r + 8];
        #pragma unroll
        for (int nt = 0; nt < 16; ++nt) {
            int j = nt * 8 + 2 * tig;
            float sy0 = sn[1][j], sy1 = sn[1][j + 1];
            float2 o0, o1;
            o0.x = sx0 + sy0 - 2.f * acc[mt][nt][0];
            o0.y = sx0 + sy1 - 2.f * acc[mt][nt][1];
            o1.x = sx1 + sy0 - 2.f * acc[mt][nt][2];
            o1.y = sx1 + sy1 - 2.f * acc[mt][nt][3];
            *reinterpret_cast<float2*>(&cb[(size_t)i0r * K_ + j])       = o0;
            *reinterpret_cast<float2*>(&cb[(size_t)(i0r + 8) * K_ + j]) = o1;
        }
    }
}

// ---------------------------------------------------------------------------
// Kernel 2: JV solver — R5-best configuration: static grid 512, ONE 32-thread
// warp per CTA, 64KB smem (3 CTAs/SM). Solver body validated since R5.
// NEW: loss is read directly from the chosen cost entries at solve end
// (MSE == sum of assigned cost entries / (B*K*D)) — the separate loss kernel
// and g_perm are eliminated (no 256MB X/Y re-stream).
// ---------------------------------------------------------------------------
__global__ void __launch_bounds__(32) hungarian_kernel()
{
    extern __shared__ float cost_s[];       // K_*K_ floats (64 KB)
    __shared__ float u_s[K_ + 4];
    __shared__ int   rowclaim[K_];
    __shared__ int   q_s[4 * K_ + 8];

    const unsigned FULL = 0xFFFFFFFFu;
    int b = blockIdx.x;
    int L = threadIdx.x;

    // ---- Stage cost matrix; fold column-reduction into the copy. ----
    float cm0 = 3.0e38f, cm1 = 3.0e38f, cm2 = 3.0e38f, cm3 = 3.0e38f;
    int   am0 = 0, am1 = 0, am2 = 0, am3 = 0;
    {
        const float4* src = reinterpret_cast<const float4*>(g_cost + (size_t)b * K_ * K_);
        float4* dst = reinterpret_cast<float4*>(cost_s);
        #pragma unroll 8
        for (int q = 0; q < K_; ++q) {
            float4 vv = src[L + 32 * q];
            dst[L + 32 * q] = vv;
            if (vv.x < cm0) { cm0 = vv.x; am0 = q; }
            if (vv.y < cm1) { cm1 = vv.y; am1 = q; }
            if (vv.z < cm2) { cm2 = vv.z; am2 = q; }
            if (vv.w < cm3) { cm3 = vv.w; am3 = q; }
        }
    }
    #pragma unroll
    for (int c = 0; c < 4; ++c) {
        u_s[1 + L + 32 * c] = 0.f;
        rowclaim[L + 32 * c] = -1;
    }
    if (L == 0) u_s[0] = 0.f;
    __syncwarp();

    // ---- Greedy claim. ----
    float v[4] = {cm0, cm1, cm2, cm3};
    int am[4] = {am0, am1, am2, am3};
    unsigned pcol_pack = 0;          // 4x8-bit: p[4L+c] (row id 1..128, 0=free)
    #pragma unroll
    for (int c = 0; c < 4; ++c) {
        if (atomicCAS(&rowclaim[am[c]], -1, 4 * L + c) == -1)
            pcol_pack |= (unsigned)(am[c] + 1) << (8 * c);
    }
    __syncwarp();

    // ---- Augmenting row reduction (lapjv ARR). ----
    {
        if (L == 0) {
            int n = 0;
            for (int r = 0; r < K_; ++r)
                if (rowclaim[r] < 0) q_s[n++] = r + 1;
            q_s[4 * K_ + 4] = n;
        }
        __syncwarp();
        int qlen = q_s[4 * K_ + 4];
        int k = 0;
        int iters = 0;
        const int cap = 3 * K_;
        while (k < qlen && iters < cap) {
            ++iters;
            int i = q_s[k]; ++k;
            const float* crow = cost_s + (size_t)(i - 1) * K_;
            float4 c4 = *reinterpret_cast<const float4*>(crow + 4 * L);
            float r0 = fmaxf(c4.x - v[0], 0.f), r1 = fmaxf(c4.y - v[1], 0.f);
            float r2 = fmaxf(c4.z - v[2], 0.f), r3 = fmaxf(c4.w - v[3], 0.f);
            float lm1 = r0, lm2 = 3.0e38f; int lc = 0, lc2 = 1;
            if (r1 < lm1) { lm2 = lm1; lc2 = lc; lm1 = r1; lc = 1; }
            else          { lm2 = r1; lc2 = 1; }
            if (r2 < lm1) { lm2 = lm1; lc2 = lc; lm1 = r2; lc = 2; }
            else if (r2 < lm2) { lm2 = r2; lc2 = 2; }
            if (r3 < lm1) { lm2 = lm1; lc2 = lc; lm1 = r3; lc = 3; }
            else if (r3 < lm2) { lm2 = r3; lc2 = 3; }

            unsigned k1 = (__float_as_uint(lm1) & 0xFFFFFF00u) | (unsigned)(4 * L + lc);
            unsigned m1 = __reduce_min_sync(FULL, k1);
            int j1_0 = m1 & 0xFF;
            int wl1 = j1_0 >> 2;
            unsigned k2 = (L == wl1)
                ? ((__float_as_uint(lm2) & 0xFFFFFF00u) | (unsigned)(4 * L + lc2))
                : k1;
            unsigned m2 = __reduce_min_sync(FULL, k2);
            int j2_0 = m2 & 0xFF;
            float u1 = __uint_as_float(m1 & 0xFFFFFF00u);
            float u2 = __uint_as_float(m2 & 0xFFFFFF00u);
            bool strict = (m1 >> 8) < (m2 >> 8);

            unsigned pp1 = __shfl_sync(FULL, pcol_pack, wl1);
            int i0 = (pp1 >> (8 * (j1_0 & 3))) & 0xFF;
            int jt_0;
            if (strict) {
                #pragma unroll
                for (int c = 0; c < 4; ++c)
                    if (L == wl1 && c == (j1_0 & 3)) v[c] -= (u2 - u1);
                jt_0 = j1_0;
            } else if (i0 != 0) {
                jt_0 = j2_0;
            } else {
                jt_0 = j1_0;
            }
            int ownt = jt_0 >> 2, slt = jt_0 & 3;
            unsigned ppt = __shfl_sync(FULL, pcol_pack, ownt);
            int idisp = (ppt >> (8 * slt)) & 0xFF;
            if (L == ownt)
                pcol_pack = (pcol_pack & ~(0xFFu << (8 * slt)))
                          | ((unsigned)i << (8 * slt));
            if (L == 0) {
                u_s[i] = u2;
                rowclaim[i - 1] = jt_0;
            }
            if (idisp != 0) {
                if (L == 0) rowclaim[idisp - 1] = -1;
                if (strict) { --k; if (L == 0) q_s[k] = idisp; }
                else        { if (L == 0) q_s[qlen] = idisp; ++qlen; }
            }
            __syncwarp();
        }
    }

    // ---- Dijkstra phases for remaining free rows. ----
    for (int i = 1; i <= K_; ++i) {
        if (rowclaim[i - 1] >= 0) continue;

        float minv[4] = {3.0e38f, 3.0e38f, 3.0e38f, 3.0e38f};
        unsigned way_pack = 0;
        unsigned used = 0;
        float urow[4];
        #pragma unroll
        for (int c = 0; c < 4; ++c)
            urow[c] = u_s[(pcol_pack >> (8 * c)) & 0xFFu];
        float ui_new = u_s[i];

        int j0 = 0, i0 = i;
        float ui0 = ui_new;
        int jfin;
        while (true) {
            float4 cr4 = *reinterpret_cast<const float4*>(
                cost_s + (size_t)(i0 - 1) * K_ + 4 * L);
            float cr[4] = {cr4.x, cr4.y, cr4.z, cr4.w};

            unsigned key = 0xFFFFFFFFu;
            float bu = 0.f;
            #pragma unroll
            for (int c = 0; c < 4; ++c) {
                bool fr = !((used >> c) & 1u);
                float cur = fmaxf(cr[c] - ui0 - v[c], 0.f);
                if (fr) {
                    if (cur < minv[c]) {
                        minv[c] = cur;
                        way_pack = (way_pack & ~(0xFFu << (8 * c)))
                                 | ((unsigned)j0 << (8 * c));
                    }
                    unsigned kc = (__float_as_uint(minv[c]) & 0xFFFFFF00u)
                                | (unsigned)(4 * L + c);
                    if (kc < key) { key = kc; bu = urow[c]; }
                }
            }
            unsigned m = __reduce_min_sync(FULL, key);
            int j1_0 = m & 0xFF;
            int wl = j1_0 >> 2, slot = j1_0 & 3;
            float ui1   = __shfl_sync(FULL, bu, wl);
            unsigned pp = __shfl_sync(FULL, pcol_pack, wl);
            int pj1 = (pp >> (8 * slot)) & 0xFF;
            float delta = __uint_as_float(m & 0xFFFFFF00u);
            #pragma unroll
            for (int c = 0; c < 4; ++c) {
                if ((used >> c) & 1u) { urow[c] += delta; v[c] -= delta; }
                else                  { minv[c] -= delta; }
            }
            ui_new += delta;
            if (L == wl) used |= 1u << slot;
            if (pj1 == 0) { jfin = j1_0 + 1; break; }
            j0 = j1_0 + 1; i0 = pj1; ui0 = ui1;
        }

        #pragma unroll
        for (int c = 0; c < 4; ++c)
            if ((used >> c) & 1u)
                u_s[(pcol_pack >> (8 * c)) & 0xFFu] = urow[c];
        if (L == 0) u_s[i] = ui_new;

        int jj = jfin;
        while (jj) {
            int idx = jj - 1;
            unsigned wp = __shfl_sync(FULL, way_pack, idx >> 2);
            int jprev = (wp >> (8 * (idx & 3))) & 0xFFu;
            int pv;
            if (jprev == 0) pv = i;
            else {
                int idx2 = jprev - 1;
                unsigned pp2 = __shfl_sync(FULL, pcol_pack, idx2 >> 2);
                pv = (pp2 >> (8 * (idx2 & 3))) & 0xFFu;
            }
            if ((idx >> 2) == L) {
                int sl = idx & 3;
                pcol_pack = (pcol_pack & ~(0xFFu << (8 * sl)))
                          | ((unsigned)pv << (8 * sl));
            }
            jj = jprev;
        }
        if (L == 0) rowclaim[i - 1] = 0;
        __syncwarp();
    }

    // ---- Fused loss: sum the chosen cost entries (no X/Y re-stream). ----
    {
        double s = 0.0;
        #pragma unroll
        for (int c = 0; c < 4; ++c) {
            int pr = (pcol_pack >> (8 * c)) & 0xFFu;    // row id 1..128
            s += (double)cost_s[(size_t)(pr - 1) * K_ + 4 * L + c];
        }
        #pragma unroll
        for (int off = 16; off; off >>= 1)
            s += __shfl_down_sync(FULL, s, off);
        if (L == 0) g_part[b] = s;
    }
}

// ---------------------------------------------------------------------------
__global__ void __launch_bounds__(512) final_kernel(float* __restrict__ out)
{
    __shared__ double s[512];
    int t = threadIdx.x;
    s[t] = g_part[t];
    __syncthreads();
    for (int stride = 256; stride; stride >>= 1) {
        if (t < stride) s[t] += s[t + stride];
        __syncthreads();
    }
    if (t == 0) out[0] = (float)(s[0] / ((double)B_ * K_ * D_));
}

// ---------------------------------------------------------------------------
extern "C" void kernel_launch(void* const* d_in, const int* in_sizes, int n_in,
                              void* d_out, int out_size)
{
    (void)in_sizes; (void)n_in; (void)out_size;
    const float* X = (const float*)d_in[0];
    const float* Y = (const float*)d_in[1];
    float* out = (float*)d_out;

    cudaFuncSetAttribute(hungarian_kernel,
                         cudaFuncAttributeMaxDynamicSharedMemorySize,
                         K_ * K_ * (int)sizeof(float));

    cost_kernel<<<B_, 128, COST_SMEM>>>(X, Y);
    hungarian_kernel<<<B_, 32, K_ * K_ * sizeof(float)>>>();
    final_kernel<<<1, 512>>>(out);
}

// round 15
// speedup vs baseline: 1.7635x; 1.0217x over previous
#include <cuda_runtime.h>
#include <cstdint>
#include <cstddef>

#define B_ 512
#define K_ 128
#define D_ 512

// Scratch (static device globals — no allocation anywhere).
__device__ float  g_cost[(size_t)B_ * K_ * K_];   // 32 MB
__device__ double g_part[B_];                     // per-batch assignment cost

// ---------------------------------------------------------------------------
// tf32 mma.sync.m16n8k8 (raw fp32 bits as tf32, RZ truncation).
// ---------------------------------------------------------------------------
__device__ __forceinline__ void mma_tf32(float* c, unsigned a0, unsigned a1,
                                         unsigned a2, unsigned a3,
                                         unsigned b0, unsigned b1)
{
    asm volatile(
        "mma.sync.aligned.m16n8k8.row.col.f32.tf32.tf32.f32 "
        "{%0,%1,%2,%3}, {%4,%5,%6,%7}, {%8,%9}, {%0,%1,%2,%3};"
        : "+f"(c[0]), "+f"(c[1]), "+f"(c[2]), "+f"(c[3])
        : "r"(a0), "r"(a1), "r"(a2), "r"(a3), "r"(b0), "r"(b1));
}

__device__ __forceinline__ void cp16(unsigned dst, const void* src)
{
    asm volatile("cp.async.cg.shared.global [%0], [%1], 16;"
                 :: "r"(dst), "l"(src));
}

#define KT 16                       // cost k-tile
#define PSTR 20                     // padded stride (floats); 80B rows, 16B aligned
#define BUF_FLOATS (K_ * PSTR)      // 2560 floats per matrix per buffer
#define COST_SMEM (4 * BUF_FLOATS * 4)   // 40 KB: 2 buffers x {x,y}

// ---------------------------------------------------------------------------
// Kernel 1: cost matrix, one CTA (4 warps) per batch, cp.async double-buffered
// tf32 MMA. Validated (R10-R14, ~152us).
// ---------------------------------------------------------------------------
__global__ void __launch_bounds__(128, 3) cost_kernel(const float* __restrict__ X,
                                                      const float* __restrict__ Y)
{
    extern __shared__ char smem_raw[];
    __shared__ float sn[2][K_];

    int b = blockIdx.x;
    int tid = threadIdx.x;
    int w = tid >> 5, lane = tid & 31;
    const float* x = X + (size_t)b * K_ * D_;
    const float* y = Y + (size_t)b * K_ * D_;

    float* stage = reinterpret_cast<float*>(smem_raw);
    unsigned stage_s = (unsigned)__cvta_generic_to_shared(stage);
    float* cb = g_cost + (size_t)b * K_ * K_;

    // Issue tile 0 loads immediately.
    {
        unsigned xb = stage_s;
        unsigned yb = xb + BUF_FLOATS * 4;
        #pragma unroll
        for (int l = 0; l < 4; ++l) {
            int cid = tid + l * 128;
            int row = cid >> 2, c4 = cid & 3;
            cp16(xb + (unsigned)(row * PSTR + c4 * 4) * 4,
                 x + (size_t)row * D_ + c4 * 4);
            cp16(yb + (unsigned)(row * PSTR + c4 * 4) * 4,
                 y + (size_t)row * D_ + c4 * 4);
        }
        asm volatile("cp.async.commit_group;");
    }

    // Row squared norms (exact fp32), overlapped with tile-0 flight.
    {
        const float4* px = reinterpret_cast<const float4*>(x + (size_t)tid * D_);
        const float4* py = reinterpret_cast<const float4*>(y + (size_t)tid * D_);
        float s0 = 0.f, s1 = 0.f;
        #pragma unroll 8
        for (int k = 0; k < D_ / 4; ++k) {
            float4 a = px[k];
            s0 += a.x * a.x + a.y * a.y + a.z * a.z + a.w * a.w;
            float4 c = py[k];
            s1 += c.x * c.x + c.y * c.y + c.z * c.z + c.w * c.w;
        }
        sn[0][tid] = s0;
        sn[1][tid] = s1;
    }

    int g = lane >> 2, tig = lane & 3;
    int m0 = w * 32;

    float acc[2][16][4];
    #pragma unroll
    for (int mt = 0; mt < 2; ++mt)
        #pragma unroll
        for (int nt = 0; nt < 16; ++nt)
            #pragma unroll
            for (int q = 0; q < 4; ++q) acc[mt][nt][q] = 0.f;

    const int NT_TILES = D_ / KT;    // 32
    for (int t = 0; t < NT_TILES; ++t) {
        if (t + 1 < NT_TILES) {
            int k0 = (t + 1) * KT;
            unsigned xb = stage_s + (unsigned)(((t + 1) & 1) * 2 * BUF_FLOATS) * 4;
            unsigned yb = xb + BUF_FLOATS * 4;
            #pragma unroll
            for (int l = 0; l < 4; ++l) {
                int cid = tid + l * 128;
                int row = cid >> 2, c4 = cid & 3;
                cp16(xb + (unsigned)(row * PSTR + c4 * 4) * 4,
                     x + (size_t)row * D_ + k0 + c4 * 4);
                cp16(yb + (unsigned)(row * PSTR + c4 * 4) * 4,
                     y + (size_t)row * D_ + k0 + c4 * 4);
            }
        }
        asm volatile("cp.async.commit_group;");   // uniform group count
        asm volatile("cp.async.wait_group 1;");   // tile t resident
        __syncthreads();

        const float* xs = stage + (t & 1) * 2 * BUF_FLOATS;
        const float* ys = xs + BUF_FLOATS;

        #pragma unroll
        for (int ks = 0; ks < KT; ks += 8) {
            unsigned a[2][4];
            #pragma unroll
            for (int mt = 0; mt < 2; ++mt) {
                int r = m0 + mt * 16 + g;
                a[mt][0] = __float_as_uint(xs[r * PSTR + ks + tig]);
                a[mt][1] = __float_as_uint(xs[(r + 8) * PSTR + ks + tig]);
                a[mt][2] = __float_as_uint(xs[r * PSTR + ks + tig + 4]);
                a[mt][3] = __float_as_uint(xs[(r + 8) * PSTR + ks + tig + 4]);
            }
            #pragma unroll
            for (int nt = 0; nt < 16; ++nt) {
                int cn = nt * 8 + g;
                unsigned b0 = __float_as_uint(ys[cn * PSTR + ks + tig]);
                unsigned b1 = __float_as_uint(ys[cn * PSTR + ks + tig + 4]);
                mma_tf32(acc[0][nt], a[0][0], a[0][1], a[0][2], a[0][3], b0, b1);
                mma_tf32(acc[1][nt], a[1][0], a[1][1], a[1][2], a[1][3], b0, b1);
            }
        }
        __syncthreads();   // compute done before buffer reuse next iter
    }

    // Epilogue -> g_cost
    #pragma unroll
    for (int mt = 0; mt < 2; ++mt) {
        int i0r = m0 + mt * 16 + g;
        float sx0 = sn[0][i0r];
        float sx1 = sn[0][i0r + 8];
        #pragma unroll
        for (int nt = 0; nt < 16; ++nt) {
            int j = nt * 8 + 2 * tig;
            float sy0 = sn[1][j], sy1 = sn[1][j + 1];
            float2 o0, o1;
            o0.x = sx0 + sy0 - 2.f * acc[mt][nt][0];
            o0.y = sx0 + sy1 - 2.f * acc[mt][nt][1];
            o1.x = sx1 + sy0 - 2.f * acc[mt][nt][2];
            o1.y = sx1 + sy1 - 2.f * acc[mt][nt][3];
            *reinterpret_cast<float2*>(&cb[(size_t)i0r * K_ + j])       = o0;
            *reinterpret_cast<float2*>(&cb[(size_t)(i0r + 8) * K_ + j]) = o1;
        }
    }
}

// ---------------------------------------------------------------------------
// Tiny pad kernels: position the hungarian kernel at process-launch #6 so the
// ncu capture (-s 5 -c 1) finally profiles the solver instead of cost/final.
// Negligible runtime (~empty launches inside the graph).
// ---------------------------------------------------------------------------
__global__ void pad_kernel() {}

// ---------------------------------------------------------------------------
// Kernel 2: JV solver — best-known config (R5/R14): static grid 512, ONE
// 32-thread warp per CTA, 64KB smem (3 CTAs/SM). Loss fused from chosen cost
// entries. CHANGE vs R14: ARR bounded to ~2 passes (cap = 2 * initial free
// rows, classic lapjv) instead of 3*K — avoids auction-style grinding on hard
// batches; leftover rows go to Dijkstra, which is bounded per phase.
// ---------------------------------------------------------------------------
__global__ void __launch_bounds__(32) hungarian_kernel()
{
    extern __shared__ float cost_s[];       // K_*K_ floats (64 KB)
    __shared__ float u_s[K_ + 4];
    __shared__ int   rowclaim[K_];
    __shared__ int   q_s[4 * K_ + 8];

    const unsigned FULL = 0xFFFFFFFFu;
    int b = blockIdx.x;
    int L = threadIdx.x;

    // ---- Stage cost matrix; fold column-reduction into the copy. ----
    float cm0 = 3.0e38f, cm1 = 3.0e38f, cm2 = 3.0e38f, cm3 = 3.0e38f;
    int   am0 = 0, am1 = 0, am2 = 0, am3 = 0;
    {
        const float4* src = reinterpret_cast<const float4*>(g_cost + (size_t)b * K_ * K_);
        float4* dst = reinterpret_cast<float4*>(cost_s);
        #pragma unroll 8
        for (int q = 0; q < K_; ++q) {
            float4 vv = src[L + 32 * q];
            dst[L + 32 * q] = vv;
            if (vv.x < cm0) { cm0 = vv.x; am0 = q; }
            if (vv.y < cm1) { cm1 = vv.y; am1 = q; }
            if (vv.z < cm2) { cm2 = vv.z; am2 = q; }
            if (vv.w < cm3) { cm3 = vv.w; am3 = q; }
        }
    }
    #pragma unroll
    for (int c = 0; c < 4; ++c) {
        u_s[1 + L + 32 * c] = 0.f;
        rowclaim[L + 32 * c] = -1;
    }
    if (L == 0) u_s[0] = 0.f;
    __syncwarp();

    // ---- Greedy claim. ----
    float v[4] = {cm0, cm1, cm2, cm3};
    int am[4] = {am0, am1, am2, am3};
    unsigned pcol_pack = 0;          // 4x8-bit: p[4L+c] (row id 1..128, 0=free)
    #pragma unroll
    for (int c = 0; c < 4; ++c) {
        if (atomicCAS(&rowclaim[am[c]], -1, 4 * L + c) == -1)
            pcol_pack |= (unsigned)(am[c] + 1) << (8 * c);
    }
    __syncwarp();

    // ---- Augmenting row reduction (lapjv ARR), bounded ~2 passes. ----
    {
        if (L == 0) {
            int n = 0;
            for (int r = 0; r < K_; ++r)
                if (rowclaim[r] < 0) q_s[n++] = r + 1;
            q_s[4 * K_ + 4] = n;
        }
        __syncwarp();
        int qlen = q_s[4 * K_ + 4];
        int k = 0;
        int iters = 0;
        const int cap = 2 * qlen;            // classic lapjv: ~two passes
        while (k < qlen && iters < cap) {
            ++iters;
            int i = q_s[k]; ++k;
            const float* crow = cost_s + (size_t)(i - 1) * K_;
            float4 c4 = *reinterpret_cast<const float4*>(crow + 4 * L);
            float r0 = fmaxf(c4.x - v[0], 0.f), r1 = fmaxf(c4.y - v[1], 0.f);
            float r2 = fmaxf(c4.z - v[2], 0.f), r3 = fmaxf(c4.w - v[3], 0.f);
            float lm1 = r0, lm2 = 3.0e38f; int lc = 0, lc2 = 1;
            if (r1 < lm1) { lm2 = lm1; lc2 = lc; lm1 = r1; lc = 1; }
            else          { lm2 = r1; lc2 = 1; }
            if (r2 < lm1) { lm2 = lm1; lc2 = lc; lm1 = r2; lc = 2; }
            else if (r2 < lm2) { lm2 = r2; lc2 = 2; }
            if (r3 < lm1) { lm2 = lm1; lc2 = lc; lm1 = r3; lc = 3; }
            else if (r3 < lm2) { lm2 = r3; lc2 = 3; }

            unsigned k1 = (__float_as_uint(lm1) & 0xFFFFFF00u) | (unsigned)(4 * L + lc);
            unsigned m1 = __reduce_min_sync(FULL, k1);
            int j1_0 = m1 & 0xFF;
            int wl1 = j1_0 >> 2;
            unsigned k2 = (L == wl1)
                ? ((__float_as_uint(lm2) & 0xFFFFFF00u) | (unsigned)(4 * L + lc2))
                : k1;
            unsigned m2 = __reduce_min_sync(FULL, k2);
            int j2_0 = m2 & 0xFF;
            float u1 = __uint_as_float(m1 & 0xFFFFFF00u);
            float u2 = __uint_as_float(m2 & 0xFFFFFF00u);
            bool strict = (m1 >> 8) < (m2 >> 8);

            unsigned pp1 = __shfl_sync(FULL, pcol_pack, wl1);
            int i0 = (pp1 >> (8 * (j1_0 & 3))) & 0xFF;
            int jt_0;
            if (strict) {
                #pragma unroll
                for (int c = 0; c < 4; ++c)
                    if (L == wl1 && c == (j1_0 & 3)) v[c] -= (u2 - u1);
                jt_0 = j1_0;
            } else if (i0 != 0) {
                jt_0 = j2_0;
            } else {
                jt_0 = j1_0;
            }
            int ownt = jt_0 >> 2, slt = jt_0 & 3;
            unsigned ppt = __shfl_sync(FULL, pcol_pack, ownt);
            int idisp = (ppt >> (8 * slt)) & 0xFF;
            if (L == ownt)
                pcol_pack = (pcol_pack & ~(0xFFu << (8 * slt)))
                          | ((unsigned)i << (8 * slt));
            if (L == 0) {
                u_s[i] = u2;
                rowclaim[i - 1] = jt_0;
            }
            if (idisp != 0) {
                if (L == 0) rowclaim[idisp - 1] = -1;
                if (strict) { --k; if (L == 0) q_s[k] = idisp; }
                else        { if (L == 0) q_s[qlen] = idisp; ++qlen; }
            }
            __syncwarp();
        }
    }

    // ---- Dijkstra phases for remaining free rows. ----
    for (int i = 1; i <= K_; ++i) {
        if (rowclaim[i - 1] >= 0) continue;

        float minv[4] = {3.0e38f, 3.0e38f, 3.0e38f, 3.0e38f};
        unsigned way_pack = 0;
        unsigned used = 0;
        float urow[4];
        #pragma unroll
        for (int c = 0; c < 4; ++c)
            urow[c] = u_s[(pcol_pack >> (8 * c)) & 0xFFu];
        float ui_new = u_s[i];

        int j0 = 0, i0 = i;
        float ui0 = ui_new;
        int jfin;
        while (true) {
            float4 cr4 = *reinterpret_cast<const float4*>(
                cost_s + (size_t)(i0 - 1) * K_ + 4 * L);
            float cr[4] = {cr4.x, cr4.y, cr4.z, cr4.w};

            unsigned key = 0xFFFFFFFFu;
            float bu = 0.f;
            #pragma unroll
            for (int c = 0; c < 4; ++c) {
                bool fr = !((used >> c) & 1u);
                float cur = fmaxf(cr[c] - ui0 - v[c], 0.f);
                if (fr) {
                    if (cur < minv[c]) {
                        minv[c] = cur;
                        way_pack = (way_pack & ~(0xFFu << (8 * c)))
                                 | ((unsigned)j0 << (8 * c));
                    }
                    unsigned kc = (__float_as_uint(minv[c]) & 0xFFFFFF00u)
                                | (unsigned)(4 * L + c);
                    if (kc < key) { key = kc; bu = urow[c]; }
                }
            }
            unsigned m = __reduce_min_sync(FULL, key);
            int j1_0 = m & 0xFF;
            int wl = j1_0 >> 2, slot = j1_0 & 3;
            float ui1   = __shfl_sync(FULL, bu, wl);
            unsigned pp = __shfl_sync(FULL, pcol_pack, wl);
            int pj1 = (pp >> (8 * slot)) & 0xFF;
            float delta = __uint_as_float(m & 0xFFFFFF00u);
            #pragma unroll
            for (int c = 0; c < 4; ++c) {
                if ((used >> c) & 1u) { urow[c] += delta; v[c] -= delta; }
                else                  { minv[c] -= delta; }
            }
            ui_new += delta;
            if (L == wl) used |= 1u << slot;
            if (pj1 == 0) { jfin = j1_0 + 1; break; }
            j0 = j1_0 + 1; i0 = pj1; ui0 = ui1;
        }

        #pragma unroll
        for (int c = 0; c < 4; ++c)
            if ((used >> c) & 1u)
                u_s[(pcol_pack >> (8 * c)) & 0xFFu] = urow[c];
        if (L == 0) u_s[i] = ui_new;

        int jj = jfin;
        while (jj) {
            int idx = jj - 1;
            unsigned wp = __shfl_sync(FULL, way_pack, idx >> 2);
            int jprev = (wp >> (8 * (idx & 3))) & 0xFFu;
            int pv;
            if (jprev == 0) pv = i;
            else {
                int idx2 = jprev - 1;
                unsigned pp2 = __shfl_sync(FULL, pcol_pack, idx2 >> 2);
                pv = (pp2 >> (8 * (idx2 & 3))) & 0xFFu;
            }
            if ((idx >> 2) == L) {
                int sl = idx & 3;
                pcol_pack = (pcol_pack & ~(0xFFu << (8 * sl)))
                          | ((unsigned)pv << (8 * sl));
            }
            jj = jprev;
        }
        if (L == 0) rowclaim[i - 1] = 0;
        __syncwarp();
    }

    // ---- Fused loss: sum the chosen cost entries (no X/Y re-stream). ----
    {
        double s = 0.0;
        #pragma unroll
        for (int c = 0; c < 4; ++c) {
            int pr = (pcol_pack >> (8 * c)) & 0xFFu;    // row id 1..128
            s += (double)cost_s[(size_t)(pr - 1) * K_ + 4 * L + c];
        }
        #pragma unroll
        for (int off = 16; off; off >>= 1)
            s += __shfl_down_sync(FULL, s, off);
        if (L == 0) g_part[b] = s;
    }
}

// ---------------------------------------------------------------------------
__global__ void __launch_bounds__(512) final_kernel(float* __restrict__ out)
{
    __shared__ double s[512];
    int t = threadIdx.x;
    s[t] = g_part[t];
    __syncthreads();
    for (int stride = 256; stride; stride >>= 1) {
        if (t < stride) s[t] += s[t + stride];
        __syncthreads();
    }
    if (t == 0) out[0] = (float)(s[0] / ((double)B_ * K_ * D_));
}

// ---------------------------------------------------------------------------
extern "C" void kernel_launch(void* const* d_in, const int* in_sizes, int n_in,
                              void* d_out, int out_size)
{
    (void)in_sizes; (void)n_in; (void)out_size;
    const float* X = (const float*)d_in[0];
    const float* Y = (const float*)d_in[1];
    float* out = (float*)d_out;

    cudaFuncSetAttribute(hungarian_kernel,
                         cudaFuncAttributeMaxDynamicSharedMemorySize,
                         K_ * K_ * (int)sizeof(float));

    cost_kernel<<<B_, 128, COST_SMEM>>>(X, Y);
    // 4 pads put hungarian_kernel at process launch #6 -> ncu (-s 5 -c 1)
    // captures the solver for the first time.
    pad_kernel<<<1, 32>>>();
    pad_kernel<<<1, 32>>>();
    pad_kernel<<<1, 32>>>();
    pad_kernel<<<1, 32>>>();
    hungarian_kernel<<<B_, 32, K_ * K_ * sizeof(float)>>>();
    final_kernel<<<1, 512>>>(out);
}

// round 16
// speedup vs baseline: 1.7670x; 1.0020x over previous
#include <cuda_runtime.h>
#include <cstdint>
#include <cstddef>

#define B_ 512
#define K_ 128
#define D_ 512

// Scratch (static device globals — no allocation anywhere).
__device__ float  g_cost[(size_t)B_ * K_ * K_];   // 32 MB
__device__ double g_part[B_];                     // per-batch assignment cost

// ---------------------------------------------------------------------------
// tf32 mma.sync.m16n8k8 (raw fp32 bits as tf32, RZ truncation).
// ---------------------------------------------------------------------------
__device__ __forceinline__ void mma_tf32(float* c, unsigned a0, unsigned a1,
                                         unsigned a2, unsigned a3,
                                         unsigned b0, unsigned b1)
{
    asm volatile(
        "mma.sync.aligned.m16n8k8.row.col.f32.tf32.tf32.f32 "
        "{%0,%1,%2,%3}, {%4,%5,%6,%7}, {%8,%9}, {%0,%1,%2,%3};"
        : "+f"(c[0]), "+f"(c[1]), "+f"(c[2]), "+f"(c[3])
        : "r"(a0), "r"(a1), "r"(a2), "r"(a3), "r"(b0), "r"(b1));
}

__device__ __forceinline__ void cp16(unsigned dst, const void* src)
{
    asm volatile("cp.async.cg.shared.global [%0], [%1], 16;"
                 :: "r"(dst), "l"(src));
}

#define KT 16                       // cost k-tile
#define PSTR 20                     // padded stride (floats); 80B rows, 16B aligned
#define BUF_FLOATS (K_ * PSTR)      // 2560 floats per matrix per buffer
#define COST_SMEM (4 * BUF_FLOATS * 4)   // 40 KB: 2 buffers x {x,y}

// ---------------------------------------------------------------------------
// Kernel 1: cost matrix, one CTA (4 warps) per batch, cp.async double-buffered
// tf32 MMA. Validated (R10-R15, ~152us).
// ---------------------------------------------------------------------------
__global__ void __launch_bounds__(128, 3) cost_kernel(const float* __restrict__ X,
                                                      const float* __restrict__ Y)
{
    extern __shared__ char smem_raw[];
    __shared__ float sn[2][K_];

    int b = blockIdx.x;
    int tid = threadIdx.x;
    int w = tid >> 5, lane = tid & 31;
    const float* x = X + (size_t)b * K_ * D_;
    const float* y = Y + (size_t)b * K_ * D_;

    float* stage = reinterpret_cast<float*>(smem_raw);
    unsigned stage_s = (unsigned)__cvta_generic_to_shared(stage);
    float* cb = g_cost + (size_t)b * K_ * K_;

    // Issue tile 0 loads immediately.
    {
        unsigned xb = stage_s;
        unsigned yb = xb + BUF_FLOATS * 4;
        #pragma unroll
        for (int l = 0; l < 4; ++l) {
            int cid = tid + l * 128;
            int row = cid >> 2, c4 = cid & 3;
            cp16(xb + (unsigned)(row * PSTR + c4 * 4) * 4,
                 x + (size_t)row * D_ + c4 * 4);
            cp16(yb + (unsigned)(row * PSTR + c4 * 4) * 4,
                 y + (size_t)row * D_ + c4 * 4);
        }
        asm volatile("cp.async.commit_group;");
    }

    // Row squared norms (exact fp32), overlapped with tile-0 flight.
    {
        const float4* px = reinterpret_cast<const float4*>(x + (size_t)tid * D_);
        const float4* py = reinterpret_cast<const float4*>(y + (size_t)tid * D_);
        float s0 = 0.f, s1 = 0.f;
        #pragma unroll 8
        for (int k = 0; k < D_ / 4; ++k) {
            float4 a = px[k];
            s0 += a.x * a.x + a.y * a.y + a.z * a.z + a.w * a.w;
            float4 c = py[k];
            s1 += c.x * c.x + c.y * c.y + c.z * c.z + c.w * c.w;
        }
        sn[0][tid] = s0;
        sn[1][tid] = s1;
    }

    int g = lane >> 2, tig = lane & 3;
    int m0 = w * 32;

    float acc[2][16][4];
    #pragma unroll
    for (int mt = 0; mt < 2; ++mt)
        #pragma unroll
        for (int nt = 0; nt < 16; ++nt)
            #pragma unroll
            for (int q = 0; q < 4; ++q) acc[mt][nt][q] = 0.f;

    const int NT_TILES = D_ / KT;    // 32
    for (int t = 0; t < NT_TILES; ++t) {
        if (t + 1 < NT_TILES) {
            int k0 = (t + 1) * KT;
            unsigned xb = stage_s + (unsigned)(((t + 1) & 1) * 2 * BUF_FLOATS) * 4;
            unsigned yb = xb + BUF_FLOATS * 4;
            #pragma unroll
            for (int l = 0; l < 4; ++l) {
                int cid = tid + l * 128;
                int row = cid >> 2, c4 = cid & 3;
                cp16(xb + (unsigned)(row * PSTR + c4 * 4) * 4,
                     x + (size_t)row * D_ + k0 + c4 * 4);
                cp16(yb + (unsigned)(row * PSTR + c4 * 4) * 4,
                     y + (size_t)row * D_ + k0 + c4 * 4);
            }
        }
        asm volatile("cp.async.commit_group;");   // uniform group count
        asm volatile("cp.async.wait_group 1;");   // tile t resident
        __syncthreads();

        const float* xs = stage + (t & 1) * 2 * BUF_FLOATS;
        const float* ys = xs + BUF_FLOATS;

        #pragma unroll
        for (int ks = 0; ks < KT; ks += 8) {
            unsigned a[2][4];
            #pragma unroll
            for (int mt = 0; mt < 2; ++mt) {
                int r = m0 + mt * 16 + g;
                a[mt][0] = __float_as_uint(xs[r * PSTR + ks + tig]);
                a[mt][1] = __float_as_uint(xs[(r + 8) * PSTR + ks + tig]);
                a[mt][2] = __float_as_uint(xs[r * PSTR + ks + tig + 4]);
                a[mt][3] = __float_as_uint(xs[(r + 8) * PSTR + ks + tig + 4]);
            }
            #pragma unroll
            for (int nt = 0; nt < 16; ++nt) {
                int cn = nt * 8 + g;
                unsigned b0 = __float_as_uint(ys[cn * PSTR + ks + tig]);
                unsigned b1 = __float_as_uint(ys[cn * PSTR + ks + tig + 4]);
                mma_tf32(acc[0][nt], a[0][0], a[0][1], a[0][2], a[0][3], b0, b1);
                mma_tf32(acc[1][nt], a[1][0], a[1][1], a[1][2], a[1][3], b0, b1);
            }
        }
        __syncthreads();   // compute done before buffer reuse next iter
    }

    // Epilogue -> g_cost
    #pragma unroll
    for (int mt = 0; mt < 2; ++mt) {
        int i0r = m0 + mt * 16 + g;
        float sx0 = sn[0][i0r];
        float sx1 = sn[0][i0r + 8];
        #pragma unroll
        for (int nt = 0; nt < 16; ++nt) {
            int j = nt * 8 + 2 * tig;
            float sy0 = sn[1][j], sy1 = sn[1][j + 1];
            float2 o0, o1;
            o0.x = sx0 + sy0 - 2.f * acc[mt][nt][0];
            o0.y = sx0 + sy1 - 2.f * acc[mt][nt][1];
            o1.x = sx1 + sy0 - 2.f * acc[mt][nt][2];
            o1.y = sx1 + sy1 - 2.f * acc[mt][nt][3];
            *reinterpret_cast<float2*>(&cb[(size_t)i0r * K_ + j])       = o0;
            *reinterpret_cast<float2*>(&cb[(size_t)(i0r + 8) * K_ + j]) = o1;
        }
    }
}

// ---------------------------------------------------------------------------
// Pad kernels: R15 showed the capture (-s 5 -c 1) lands one launch EARLIER
// than computed (it hit pad #4) — there is one extra process launch ahead of
// ours. Five pads put hungarian_kernel exactly in the capture slot.
// ---------------------------------------------------------------------------
__global__ void pad_kernel() {}

// ---------------------------------------------------------------------------
// Kernel 2: JV solver — best-known config: static grid 512, ONE 32-thread
// warp per CTA, 64KB smem (3 CTAs/SM). ARR bounded to ~2 passes (R15 win).
// Loss fused from chosen cost entries (R14 win).
// ---------------------------------------------------------------------------
__global__ void __launch_bounds__(32) hungarian_kernel()
{
    extern __shared__ float cost_s[];       // K_*K_ floats (64 KB)
    __shared__ float u_s[K_ + 4];
    __shared__ int   rowclaim[K_];
    __shared__ int   q_s[4 * K_ + 8];

    const unsigned FULL = 0xFFFFFFFFu;
    int b = blockIdx.x;
    int L = threadIdx.x;

    // ---- Stage cost matrix; fold column-reduction into the copy. ----
    float cm0 = 3.0e38f, cm1 = 3.0e38f, cm2 = 3.0e38f, cm3 = 3.0e38f;
    int   am0 = 0, am1 = 0, am2 = 0, am3 = 0;
    {
        const float4* src = reinterpret_cast<const float4*>(g_cost + (size_t)b * K_ * K_);
        float4* dst = reinterpret_cast<float4*>(cost_s);
        #pragma unroll 8
        for (int q = 0; q < K_; ++q) {
            float4 vv = src[L + 32 * q];
            dst[L + 32 * q] = vv;
            if (vv.x < cm0) { cm0 = vv.x; am0 = q; }
            if (vv.y < cm1) { cm1 = vv.y; am1 = q; }
            if (vv.z < cm2) { cm2 = vv.z; am2 = q; }
            if (vv.w < cm3) { cm3 = vv.w; am3 = q; }
        }
    }
    #pragma unroll
    for (int c = 0; c < 4; ++c) {
        u_s[1 + L + 32 * c] = 0.f;
        rowclaim[L + 32 * c] = -1;
    }
    if (L == 0) u_s[0] = 0.f;
    __syncwarp();

    // ---- Greedy claim. ----
    float v[4] = {cm0, cm1, cm2, cm3};
    int am[4] = {am0, am1, am2, am3};
    unsigned pcol_pack = 0;          // 4x8-bit: p[4L+c] (row id 1..128, 0=free)
    #pragma unroll
    for (int c = 0; c < 4; ++c) {
        if (atomicCAS(&rowclaim[am[c]], -1, 4 * L + c) == -1)
            pcol_pack |= (unsigned)(am[c] + 1) << (8 * c);
    }
    __syncwarp();

    // ---- Augmenting row reduction (lapjv ARR), bounded ~2 passes. ----
    {
        if (L == 0) {
            int n = 0;
            for (int r = 0; r < K_; ++r)
                if (rowclaim[r] < 0) q_s[n++] = r + 1;
            q_s[4 * K_ + 4] = n;
        }
        __syncwarp();
        int qlen = q_s[4 * K_ + 4];
        int k = 0;
        int iters = 0;
        const int cap = 2 * qlen;            // classic lapjv: ~two passes
        while (k < qlen && iters < cap) {
            ++iters;
            int i = q_s[k]; ++k;
            const float* crow = cost_s + (size_t)(i - 1) * K_;
            float4 c4 = *reinterpret_cast<const float4*>(crow + 4 * L);
            float r0 = fmaxf(c4.x - v[0], 0.f), r1 = fmaxf(c4.y - v[1], 0.f);
            float r2 = fmaxf(c4.z - v[2], 0.f), r3 = fmaxf(c4.w - v[3], 0.f);
            float lm1 = r0, lm2 = 3.0e38f; int lc = 0, lc2 = 1;
            if (r1 < lm1) { lm2 = lm1; lc2 = lc; lm1 = r1; lc = 1; }
            else          { lm2 = r1; lc2 = 1; }
            if (r2 < lm1) { lm2 = lm1; lc2 = lc; lm1 = r2; lc = 2; }
            else if (r2 < lm2) { lm2 = r2; lc2 = 2; }
            if (r3 < lm1) { lm2 = lm1; lc2 = lc; lm1 = r3; lc = 3; }
            else if (r3 < lm2) { lm2 = r3; lc2 = 3; }

            unsigned k1 = (__float_as_uint(lm1) & 0xFFFFFF00u) | (unsigned)(4 * L + lc);
            unsigned m1 = __reduce_min_sync(FULL, k1);
            int j1_0 = m1 & 0xFF;
            int wl1 = j1_0 >> 2;
            unsigned k2 = (L == wl1)
                ? ((__float_as_uint(lm2) & 0xFFFFFF00u) | (unsigned)(4 * L + lc2))
                : k1;
            unsigned m2 = __reduce_min_sync(FULL, k2);
            int j2_0 = m2 & 0xFF;
            float u1 = __uint_as_float(m1 & 0xFFFFFF00u);
            float u2 = __uint_as_float(m2 & 0xFFFFFF00u);
            bool strict = (m1 >> 8) < (m2 >> 8);

            unsigned pp1 = __shfl_sync(FULL, pcol_pack, wl1);
            int i0 = (pp1 >> (8 * (j1_0 & 3))) & 0xFF;
            int jt_0;
            if (strict) {
                #pragma unroll
                for (int c = 0; c < 4; ++c)
                    if (L == wl1 && c == (j1_0 & 3)) v[c] -= (u2 - u1);
                jt_0 = j1_0;
            } else if (i0 != 0) {
                jt_0 = j2_0;
            } else {
                jt_0 = j1_0;
            }
            int ownt = jt_0 >> 2, slt = jt_0 & 3;
            unsigned ppt = __shfl_sync(FULL, pcol_pack, ownt);
            int idisp = (ppt >> (8 * slt)) & 0xFF;
            if (L == ownt)
                pcol_pack = (pcol_pack & ~(0xFFu << (8 * slt)))
                          | ((unsigned)i << (8 * slt));
            if (L == 0) {
                u_s[i] = u2;
                rowclaim[i - 1] = jt_0;
            }
            if (idisp != 0) {
                if (L == 0) rowclaim[idisp - 1] = -1;
                if (strict) { --k; if (L == 0) q_s[k] = idisp; }
                else        { if (L == 0) q_s[qlen] = idisp; ++qlen; }
            }
            __syncwarp();
        }
    }

    // ---- Dijkstra phases for remaining free rows. ----
    for (int i = 1; i <= K_; ++i) {
        if (rowclaim[i - 1] >= 0) continue;

        float minv[4] = {3.0e38f, 3.0e38f, 3.0e38f, 3.0e38f};
        unsigned way_pack = 0;
        unsigned used = 0;
        float urow[4];
        #pragma unroll
        for (int c = 0; c < 4; ++c)
            urow[c] = u_s[(pcol_pack >> (8 * c)) & 0xFFu];
        float ui_new = u_s[i];

        int j0 = 0, i0 = i;
        float ui0 = ui_new;
        int jfin;
        while (true) {
            float4 cr4 = *reinterpret_cast<const float4*>(
                cost_s + (size_t)(i0 - 1) * K_ + 4 * L);
            float cr[4] = {cr4.x, cr4.y, cr4.z, cr4.w};

            unsigned key = 0xFFFFFFFFu;
            float bu = 0.f;
            #pragma unroll
            for (int c = 0; c < 4; ++c) {
                bool fr = !((used >> c) & 1u);
                float cur = fmaxf(cr[c] - ui0 - v[c], 0.f);
                if (fr) {
                    if (cur < minv[c]) {
                        minv[c] = cur;
                        way_pack = (way_pack & ~(0xFFu << (8 * c)))
                                 | ((unsigned)j0 << (8 * c));
                    }
                    unsigned kc = (__float_as_uint(minv[c]) & 0xFFFFFF00u)
                                | (unsigned)(4 * L + c);
                    if (kc < key) { key = kc; bu = urow[c]; }
                }
            }
            unsigned m = __reduce_min_sync(FULL, key);
            int j1_0 = m & 0xFF;
            int wl = j1_0 >> 2, slot = j1_0 & 3;
            float ui1   = __shfl_sync(FULL, bu, wl);
            unsigned pp = __shfl_sync(FULL, pcol_pack, wl);
            int pj1 = (pp >> (8 * slot)) & 0xFF;
            float delta = __uint_as_float(m & 0xFFFFFF00u);
            #pragma unroll
            for (int c = 0; c < 4; ++c) {
                if ((used >> c) & 1u) { urow[c] += delta; v[c] -= delta; }
                else                  { minv[c] -= delta; }
            }
            ui_new += delta;
            if (L == wl) used |= 1u << slot;
            if (pj1 == 0) { jfin = j1_0 + 1; break; }
            j0 = j1_0 + 1; i0 = pj1; ui0 = ui1;
        }

        #pragma unroll
        for (int c = 0; c < 4; ++c)
            if ((used >> c) & 1u)
                u_s[(pcol_pack >> (8 * c)) & 0xFFu] = urow[c];
        if (L == 0) u_s[i] = ui_new;

        int jj = jfin;
        while (jj) {
            int idx = jj - 1;
            unsigned wp = __shfl_sync(FULL, way_pack, idx >> 2);
            int jprev = (wp >> (8 * (idx & 3))) & 0xFFu;
            int pv;
            if (jprev == 0) pv = i;
            else {
                int idx2 = jprev - 1;
                unsigned pp2 = __shfl_sync(FULL, pcol_pack, idx2 >> 2);
                pv = (pp2 >> (8 * (idx2 & 3))) & 0xFFu;
            }
            if ((idx >> 2) == L) {
                int sl = idx & 3;
                pcol_pack = (pcol_pack & ~(0xFFu << (8 * sl)))
                          | ((unsigned)pv << (8 * sl));
            }
            jj = jprev;
        }
        if (L == 0) rowclaim[i - 1] = 0;
        __syncwarp();
    }

    // ---- Fused loss: sum the chosen cost entries (no X/Y re-stream). ----
    {
        double s = 0.0;
        #pragma unroll
        for (int c = 0; c < 4; ++c) {
            int pr = (pcol_pack >> (8 * c)) & 0xFFu;    // row id 1..128
            s += (double)cost_s[(size_t)(pr - 1) * K_ + 4 * L + c];
        }
        #pragma unroll
        for (int off = 16; off; off >>= 1)
            s += __shfl_down_sync(FULL, s, off);
        if (L == 0) g_part[b] = s;
    }
}

// ---------------------------------------------------------------------------
__global__ void __launch_bounds__(512) final_kernel(float* __restrict__ out)
{
    __shared__ double s[512];
    int t = threadIdx.x;
    s[t] = g_part[t];
    __syncthreads();
    for (int stride = 256; stride; stride >>= 1) {
        if (t < stride) s[t] += s[t + stride];
        __syncthreads();
    }
    if (t == 0) out[0] = (float)(s[0] / ((double)B_ * K_ * D_));
}

// ---------------------------------------------------------------------------
extern "C" void kernel_launch(void* const* d_in, const int* in_sizes, int n_in,
                              void* d_out, int out_size)
{
    (void)in_sizes; (void)n_in; (void)out_size;
    const float* X = (const float*)d_in[0];
    const float* Y = (const float*)d_in[1];
    float* out = (float*)d_out;

    cudaFuncSetAttribute(hungarian_kernel,
                         cudaFuncAttributeMaxDynamicSharedMemorySize,
                         K_ * K_ * (int)sizeof(float));

    cost_kernel<<<B_, 128, COST_SMEM>>>(X, Y);
    // 5 pads: R15 capture hit pad #4, i.e. one extra process launch precedes
    // ours -> shift hungarian one slot later into the capture window.
    pad_kernel<<<1, 32>>>();
    pad_kernel<<<1, 32>>>();
    pad_kernel<<<1, 32>>>();
    pad_kernel<<<1, 32>>>();
    pad_kernel<<<1, 32>>>();
    hungarian_kernel<<<B_, 32, K_ * K_ * sizeof(float)>>>();
    final_kernel<<<1, 512>>>(out);
}